// round 10
// baseline (speedup 1.0000x reference)
#include <cuda_runtime.h>

#define NB 16
#define NN 1024
#define ND 1024
#define NU 512
#define GRID_BLKS 296
#define TPB 512

// Scratch (device globals — no allocation allowed).
// g_vh/g_vm: fold accumulators, zero at load, re-zeroed in phase C each call.
__device__ float g_vh[ND];
__device__ float g_vm[ND];
__device__ float g_c;
__device__ float g_sH[NB * NN];
__device__ float g_sM[NB * NN];
// Grid barrier state: monotonically increasing ticket/generation, so it is
// reusable across graph replays without reset.
__device__ unsigned g_cnt = 0;
__device__ unsigned g_gen = 0;

__device__ __forceinline__ void grid_sync() {
    __syncthreads();
    if (threadIdx.x == 0) {
        __threadfence();
        const unsigned t   = atomicAdd(&g_cnt, 1u);
        const unsigned gen = t / GRID_BLKS + 1u;          // generation to reach
        if ((t % GRID_BLKS) == GRID_BLKS - 1u) {
            atomicExch(&g_gen, gen);                      // release
        } else {
            while (*(volatile unsigned*)&g_gen < gen) __nanosleep(32);
        }
        __threadfence();
    }
    __syncthreads();
}

// ---------------------------------------------------------------------------
// Fused persistent kernel: fold -> barrier -> rowdots -> barrier -> outer.
// 296 blocks x 512 threads, 2 CTAs/SM => co-resident (deadlock-free barrier).
// ---------------------------------------------------------------------------
__global__ void __launch_bounds__(TPB, 2) k_fused(
    const float* __restrict__ x, const float* __restrict__ W_h,
    const float* __restrict__ b_h, const float* __restrict__ W_m,
    const float* __restrict__ b_m, const float* __restrict__ w_out,
    const float* __restrict__ b_out, float* __restrict__ out)
{
    __shared__ float4 sbuf[TPB];      // 8 KB, reused by all phases
    const int tid = threadIdx.x;
    const int bid = blockIdx.x;

    // ---------------- Phase A: fold the U dimension --------------------
    // 256 tile-blocks: [32u x 32d4] tile of W_h (bid<128) or W_m.
    // Thread: 2 independent coalesced LDG.128 (u0, u0+16), smem tree over the
    // 16 thread-row-groups, 16 atomics per address grid-wide.
    if (bid < 256) {
        const bool is_h  = bid < 128;
        const int  r     = bid & 127;
        const int  utile = r >> 3;            // 0..15
        const int  dtile = r & 7;             // 0..7
        const int  d4    = dtile * 32 + (tid & 31);
        const int  urow  = tid >> 5;          // 0..15
        const float4* W4 = reinterpret_cast<const float4*>(is_h ? W_h : W_m);

        const int u0 = utile * 32 + urow;
        const int u1 = u0 + 16;
        const float  w0 = __ldg(&w_out[u0]);
        const float  w1 = __ldg(&w_out[u1]);
        const float4 v0 = __ldg(W4 + (size_t)u0 * (ND / 4) + d4);
        const float4 v1 = __ldg(W4 + (size_t)u1 * (ND / 4) + d4);

        float4 a;
        a.x = fmaf(w1, v1.x, w0 * v0.x); a.y = fmaf(w1, v1.y, w0 * v0.y);
        a.z = fmaf(w1, v1.z, w0 * v0.z); a.w = fmaf(w1, v1.w, w0 * v0.w);
        sbuf[tid] = a;
        __syncthreads();
        #pragma unroll
        for (int s = 256; s >= 32; s >>= 1) {
            if (tid < s) {
                const float4 p = sbuf[tid], q = sbuf[tid + s];
                sbuf[tid] = make_float4(p.x + q.x, p.y + q.y, p.z + q.z, p.w + q.w);
            }
            __syncthreads();
        }
        if (tid < 32) {
            float* dst = is_h ? g_vh : g_vm;
            const float4 v = sbuf[tid];
            const int d = (dtile * 32 + tid) * 4;
            atomicAdd(&dst[d + 0], v.x); atomicAdd(&dst[d + 1], v.y);
            atomicAdd(&dst[d + 2], v.z); atomicAdd(&dst[d + 3], v.w);
        }
    } else if (bid == 256) {
        // scalar constant c = w_out.(b_h+b_m) + b_out  (NU == TPB)
        float* red = reinterpret_cast<float*>(sbuf);
        red[tid] = w_out[tid] * (b_h[tid] + b_m[tid]);
        __syncthreads();
        #pragma unroll
        for (int s = 256; s > 0; s >>= 1) {
            if (tid < s) red[tid] += red[tid + s];
            __syncthreads();
        }
        if (tid == 0) g_c = red[0] + b_out[0];
    }

    grid_sync();

    // ---------------- Phase B: per-token dual dot products -------------
    // sbuf[0..255] = v_h (float4), sbuf[256..511] = v_m.
    sbuf[tid] = (tid < 256)
        ? reinterpret_cast<const float4*>(g_vh)[tid]
        : reinterpret_cast<const float4*>(g_vm)[tid - 256];
    __syncthreads();

    {
        const int warp = tid >> 5, lane = tid & 31;
        const float cc = g_c;
        for (int row = bid * 16 + warp; row < NB * NN; row += GRID_BLKS * 16) {
            const float4* x4 = reinterpret_cast<const float4*>(x) + (size_t)row * (ND / 4);
            float ah = 0.f, am = 0.f;
            #pragma unroll
            for (int k = 0; k < 8; ++k) {
                const int idx = k * 32 + lane;
                const float4 xv = __ldcs(&x4[idx]);
                const float4 vh = sbuf[idx];
                const float4 vm = sbuf[256 + idx];
                ah = fmaf(xv.x, vh.x, ah); ah = fmaf(xv.y, vh.y, ah);
                ah = fmaf(xv.z, vh.z, ah); ah = fmaf(xv.w, vh.w, ah);
                am = fmaf(xv.x, vm.x, am); am = fmaf(xv.y, vm.y, am);
                am = fmaf(xv.z, vm.z, am); am = fmaf(xv.w, vm.w, am);
            }
            #pragma unroll
            for (int off = 16; off; off >>= 1) {
                ah += __shfl_xor_sync(0xffffffffu, ah, off);
                am += __shfl_xor_sync(0xffffffffu, am, off);
            }
            if (lane == 0) {
                g_sH[row] = ah + cc;
                g_sM[row] = am;
            }
        }
    }

    grid_sync();

    // ---------------- Phase C: outer broadcast-add + re-zero ------------
    {
        const unsigned gt = bid * TPB + tid;              // 0..151551
        const unsigned total4 = (NB * NN * NN) / 4;       // 4,194,304 float4
        const float4* sM4 = reinterpret_cast<const float4*>(g_sM);
        float4* out4 = reinterpret_cast<float4*>(out);

        for (unsigned idx = gt; idx < total4; idx += GRID_BLKS * TPB) {
            const unsigned j4 = idx & 255u;   // j/4
            const unsigned bi = idx >> 8;     // b*N + i
            const unsigned b  = bi >> 10;
            const float s = g_sH[bi];
            const float4 m = sM4[(b << 8) + j4];
            out4[idx] = make_float4(s + m.x, s + m.y, s + m.z, s + m.w);
        }

        if (gt < 512) {                       // re-zero fold accumulators
            const float4 z = make_float4(0.f, 0.f, 0.f, 0.f);
            if (gt < 256) reinterpret_cast<float4*>(g_vh)[gt] = z;
            else          reinterpret_cast<float4*>(g_vm)[gt - 256] = z;
        }
    }
}

extern "C" void kernel_launch(void* const* d_in, const int* in_sizes, int n_in,
                              void* d_out, int out_size) {
    const float* x     = (const float*)d_in[0];
    const float* W_h   = (const float*)d_in[1];
    const float* b_h   = (const float*)d_in[2];
    const float* W_m   = (const float*)d_in[3];
    const float* b_m   = (const float*)d_in[4];
    const float* w_out = (const float*)d_in[5];
    const float* b_out = (const float*)d_in[6];
    float* out = (float*)d_out;

    k_fused<<<GRID_BLKS, TPB>>>(x, W_h, b_h, W_m, b_m, w_out, b_out, out);
}

// round 11
// speedup vs baseline: 1.0242x; 1.0242x over previous
#include <cuda_runtime.h>

#define NB 16
#define NN 1024
#define ND 1024
#define NU 512

// Scratch (device globals — no allocation allowed).
// g_vh/g_vm are accumulators: zero at module load, re-zeroed at the end of
// k_outer each call, so every kernel_launch sees them zeroed.
__device__ float g_vh[ND];
__device__ float g_vm[ND];
__device__ float g_c;                 // w_out.(b_h+b_m) + b_out
__device__ float g_sH[NB * NN];       // c folded in by k_rowdots
__device__ float g_sM[NB * NN];

// ---- packed f32x2 helpers (sm_103a FFMA2 path, PTX-only) -------------------
__device__ __forceinline__ unsigned long long pk2(float lo, float hi) {
    unsigned long long r;
    asm("mov.b64 %0, {%1, %2};" : "=l"(r) : "f"(lo), "f"(hi));
    return r;
}
__device__ __forceinline__ void fma2(unsigned long long& d,
                                     unsigned long long a, unsigned long long b) {
    asm("fma.rn.f32x2 %0, %1, %2, %0;" : "+l"(d) : "l"(a), "l"(b));
}
__device__ __forceinline__ float hsum2(unsigned long long v) {
    float lo, hi;
    asm("mov.b64 {%0, %1}, %2;" : "=f"(lo), "=f"(hi) : "l"(v));
    return lo + hi;
}

// ---------------------------------------------------------------------------
// Kernel 1: fold the U dimension (R9 geometry — measured 5.2us).
// Blocks 0..255: [32u x 128d] tile of W_h (bid<128) or W_m; 4 independent
// coalesced LDG.128 per thread, 3-round smem tree, 16 atomics/address.
// Block 256: scalar constant c.
// ---------------------------------------------------------------------------
__global__ void k_fold(const float* __restrict__ W_h, const float* __restrict__ W_m,
                       const float* __restrict__ w_out, const float* __restrict__ b_h,
                       const float* __restrict__ b_m, const float* __restrict__ b_out) {
    const int tid = threadIdx.x;

    if (blockIdx.x < 256) {
        const bool is_h = blockIdx.x < 128;
        const int t = is_h ? blockIdx.x : blockIdx.x - 128;
        const int utile = t >> 3;            // 0..15
        const int dtile = t & 7;             // 0..7
        const int wgrp  = tid >> 5;          // 0..7
        const int d4    = dtile * 32 + (tid & 31);

        const float4* W4 = reinterpret_cast<const float4*>(is_h ? W_h : W_m);
        const int u_base = utile * 32 + wgrp;

        float4 acc = make_float4(0.f, 0.f, 0.f, 0.f);
        #pragma unroll
        for (int k = 0; k < 4; ++k) {
            const int u = u_base + k * 8;
            const float w = __ldg(&w_out[u]);
            const float4 v = __ldg(W4 + (size_t)u * (ND / 4) + d4);
            acc.x = fmaf(w, v.x, acc.x); acc.y = fmaf(w, v.y, acc.y);
            acc.z = fmaf(w, v.z, acc.z); acc.w = fmaf(w, v.w, acc.w);
        }

        __shared__ float4 sp[256];
        sp[tid] = acc;
        __syncthreads();
        #pragma unroll
        for (int s = 128; s >= 32; s >>= 1) {
            if (tid < s) {
                float4 a = sp[tid], b = sp[tid + s];
                sp[tid] = make_float4(a.x + b.x, a.y + b.y, a.z + b.z, a.w + b.w);
            }
            __syncthreads();
        }
        if (tid < 32) {
            float* dst = is_h ? g_vh : g_vm;
            const float4 r = sp[tid];
            const int d = (dtile * 32 + tid) * 4;
            atomicAdd(&dst[d + 0], r.x); atomicAdd(&dst[d + 1], r.y);
            atomicAdd(&dst[d + 2], r.z); atomicAdd(&dst[d + 3], r.w);
        }
    } else {
        __shared__ float red[256];
        float acc = 0.f;
        for (int u = tid; u < NU; u += 256)
            acc = fmaf(w_out[u], b_h[u] + b_m[u], acc);
        red[tid] = acc;
        __syncthreads();
        for (int s = 128; s > 0; s >>= 1) {
            if (tid < s) red[tid] += red[tid + s];
            __syncthreads();
        }
        if (tid == 0) g_c = red[0] + b_out[0];
    }
}

// ---------------------------------------------------------------------------
// Kernel 2: per-token dual dot products.
// Each warp handles TWO rows (row, row+8192): 16 in-flight LDG.128/thread,
// smem vector reads amortized over both rows. Packed fma.rn.f32x2 cuts the
// FFMA warp-instruction count 4x vs scalar (32 vs 128 per row).
// x read exactly once (streaming): 64 MiB.
// ---------------------------------------------------------------------------
__global__ void k_rowdots(const float* __restrict__ x) {
    __shared__ ulonglong2 svh[ND / 4];     // each entry = 4 floats (2 x f32x2)
    __shared__ ulonglong2 svm[ND / 4];
    const int tid = threadIdx.x;           // 256 threads = 8 warps
    svh[tid] = reinterpret_cast<const ulonglong2*>(g_vh)[tid];
    svm[tid] = reinterpret_cast<const ulonglong2*>(g_vm)[tid];
    __syncthreads();

    const int warp = tid >> 5, lane = tid & 31;
    const int row0 = blockIdx.x * 8 + warp;       // 0..8191
    const int row1 = row0 + 8192;                 // 8192..16383
    const float4* xa = reinterpret_cast<const float4*>(x) + (size_t)row0 * (ND / 4);
    const float4* xb = reinterpret_cast<const float4*>(x) + (size_t)row1 * (ND / 4);

    unsigned long long h0a = 0ull, h0b = 0ull, m0a = 0ull, m0b = 0ull;  // row0
    unsigned long long h1a = 0ull, h1b = 0ull, m1a = 0ull, m1b = 0ull;  // row1

    #pragma unroll
    for (int k = 0; k < 8; ++k) {
        const int idx = k * 32 + lane;
        const float4 x0 = __ldcs(&xa[idx]);
        const float4 x1 = __ldcs(&xb[idx]);
        const ulonglong2 vh = svh[idx];
        const ulonglong2 vm = svm[idx];

        const unsigned long long x0lo = pk2(x0.x, x0.y), x0hi = pk2(x0.z, x0.w);
        const unsigned long long x1lo = pk2(x1.x, x1.y), x1hi = pk2(x1.z, x1.w);

        fma2(h0a, x0lo, vh.x); fma2(h0b, x0hi, vh.y);
        fma2(m0a, x0lo, vm.x); fma2(m0b, x0hi, vm.y);
        fma2(h1a, x1lo, vh.x); fma2(h1b, x1hi, vh.y);
        fma2(m1a, x1lo, vm.x); fma2(m1b, x1hi, vm.y);
    }

    float ah0 = hsum2(h0a) + hsum2(h0b);
    float am0 = hsum2(m0a) + hsum2(m0b);
    float ah1 = hsum2(h1a) + hsum2(h1b);
    float am1 = hsum2(m1a) + hsum2(m1b);

    #pragma unroll
    for (int off = 16; off; off >>= 1) {
        ah0 += __shfl_xor_sync(0xffffffffu, ah0, off);
        am0 += __shfl_xor_sync(0xffffffffu, am0, off);
        ah1 += __shfl_xor_sync(0xffffffffu, ah1, off);
        am1 += __shfl_xor_sync(0xffffffffu, am1, off);
    }
    if (lane == 0) {
        const float cc = g_c;
        g_sH[row0] = ah0 + cc;
        g_sM[row0] = am0;
        g_sH[row1] = ah1 + cc;
        g_sM[row1] = am1;
    }
}

// ---------------------------------------------------------------------------
// Kernel 3: outer broadcast-add. scores[b,i,j] = sH[b,i] + sM[b,j].
// Grid-stride, 4 float4 per thread, fully coalesced. Tail: re-zero the fold
// accumulators so the next kernel_launch call sees zeros.
// ---------------------------------------------------------------------------
__global__ void k_outer(float* __restrict__ out) {
    const unsigned stride = 2048u * 512u;                 // 1,048,576 float4
    unsigned idx = blockIdx.x * 512u + threadIdx.x;
    const unsigned t0 = idx;

    #pragma unroll
    for (int t = 0; t < 4; ++t, idx += stride) {
        const unsigned j4 = idx & 255u;    // j/4, N/4 = 256
        const unsigned bi = idx >> 8;      // b*N + i
        const unsigned b  = bi >> 10;      // /N

        const float s = g_sH[bi];
        const float4 m = reinterpret_cast<const float4*>(g_sM)[(b << 8) + j4];
        reinterpret_cast<float4*>(out)[idx] =
            make_float4(s + m.x, s + m.y, s + m.z, s + m.w);
    }

    if (t0 < 512) {                        // re-zero accumulators (float4)
        const float4 z = make_float4(0.f, 0.f, 0.f, 0.f);
        if (t0 < 256) reinterpret_cast<float4*>(g_vh)[t0] = z;
        else          reinterpret_cast<float4*>(g_vm)[t0 - 256] = z;
    }
}

extern "C" void kernel_launch(void* const* d_in, const int* in_sizes, int n_in,
                              void* d_out, int out_size) {
    const float* x     = (const float*)d_in[0];
    const float* W_h   = (const float*)d_in[1];
    const float* b_h   = (const float*)d_in[2];
    const float* W_m   = (const float*)d_in[3];
    const float* b_m   = (const float*)d_in[4];
    const float* w_out = (const float*)d_in[5];
    const float* b_out = (const float*)d_in[6];
    float* out = (float*)d_out;

    k_fold<<<257, 256>>>(W_h, W_m, w_out, b_h, b_m, b_out);
    k_rowdots<<<1024, 256>>>(x);
    k_outer<<<2048, 512>>>(out);
}